// round 15
// baseline (speedup 1.0000x reference)
#include <cuda_runtime.h>
#include <cuda_bf16.h>
#include <cuda_fp16.h>
#include <cstdint>

#define BB   4
#define SS   2048
#define HIDD 1024
#define NH   16
#define NKV  4
#define HD   64
#define GROUPS 4
#define SCALE_F 0.125f
#define LOG2E 1.4426950408889634f

// ---------------- scratch (__device__ globals, allocation-free) -------------
__device__ float g_q[BB*NH*SS*HD];
__device__ float g_k[BB*NKV*SS*HD];
__device__ __half g_qf[BB*NH*SS*HD];      // Q single fp16 (scaled, exp2 domain)
__device__ __half g_kf[BB*NKV*SS*HD];     // K single fp16
__device__ __half g_vf[BB*NKV*SS*HD];     // V single fp16
__device__ __half g_xf[BB*SS*HIDD];       // X single fp16
__device__ __half g_aof[BB*SS*NH*HD];     // attn out single fp16
__device__ __half g_wqf[NH*HD*HIDD];      // weights single fp16
__device__ __half g_wkf[NKV*HD*HIDD];
__device__ __half g_wvf[NKV*HD*HIDD];
__device__ __half g_wof[HIDD*NH*HD];

// ---------------- helpers ---------------------------------------------------
__device__ __forceinline__ uint32_t s2u(const void* p) {
    return (uint32_t)__cvta_generic_to_shared(p);
}
__device__ __forceinline__ void mma16816h(float* c, const uint32_t* a, const uint32_t* b) {
    asm volatile(
        "mma.sync.aligned.m16n8k16.row.col.f32.f16.f16.f32 "
        "{%0,%1,%2,%3}, {%4,%5,%6,%7}, {%8,%9}, {%0,%1,%2,%3};"
        : "+f"(c[0]), "+f"(c[1]), "+f"(c[2]), "+f"(c[3])
        : "r"(a[0]), "r"(a[1]), "r"(a[2]), "r"(a[3]), "r"(b[0]), "r"(b[1]));
}
__device__ __forceinline__ void ldsm4(uint32_t* r, uint32_t addr) {
    asm volatile("ldmatrix.sync.aligned.m8n8.x4.shared.b16 {%0,%1,%2,%3}, [%4];"
        : "=r"(r[0]), "=r"(r[1]), "=r"(r[2]), "=r"(r[3]) : "r"(addr));
}
__device__ __forceinline__ void ldsm4t(uint32_t* r, uint32_t addr) {
    asm volatile("ldmatrix.sync.aligned.m8n8.x4.trans.shared.b16 {%0,%1,%2,%3}, [%4];"
        : "=r"(r[0]), "=r"(r[1]), "=r"(r[2]), "=r"(r[3]) : "r"(addr));
}
__device__ __forceinline__ void cpa16(void* dst, const void* src) {
    asm volatile("cp.async.cg.shared.global [%0], [%1], 16;" :: "r"(s2u(dst)), "l"(src));
}
__device__ __forceinline__ void cpa_commit() {
    asm volatile("cp.async.commit_group;");
}
__device__ __forceinline__ void cpa_wait0() {
    asm volatile("cp.async.wait_group 0;" ::: "memory");
}
__device__ __forceinline__ void cpa_wait1() {
    asm volatile("cp.async.wait_group 1;" ::: "memory");
}
__device__ __forceinline__ float fexp2(float x) {
    float r;
    asm("ex2.approx.f32 %0, %1;" : "=f"(r) : "f"(x));
    return r;
}
// packed-half2 exp2: one MUFU op, output IS the fp16 A-fragment word
__device__ __forceinline__ uint32_t fexp2h2(float lo, float hi) {
    __half2 t = __floats2half2_rn(lo, hi);
    uint32_t x = *(uint32_t*)&t, r;
    asm("ex2.approx.f16x2 %0, %1;" : "=r"(r) : "r"(x));
    return r;
}
__device__ __forceinline__ void cvt4h_store(float4 v, __half* D) {
    ((__half2*)D)[0] = __floats2half2_rn(v.x, v.y);
    ((__half2*)D)[1] = __floats2half2_rn(v.z, v.w);
}

// ---------------- pre-convert: X + weights -> single fp16 -------------------
#define N4_X  (BB*SS*HIDD/4)
#define N4_WQ (NH*HD*HIDD/4)
#define N4_WK (NKV*HD*HIDD/4)
__global__ void split_all(const float* __restrict__ X,  const float* __restrict__ Wq,
                          const float* __restrict__ Wk, const float* __restrict__ Wv,
                          const float* __restrict__ Wo)
{
    int i = blockIdx.x * blockDim.x + threadIdx.x;
    const float* src; __half* dst; int off;
    if (i < N4_X)                  { src = X;  dst = g_xf;  off = i; }
    else if ((i -= N4_X)  < N4_WQ) { src = Wq; dst = g_wqf; off = i; }
    else if ((i -= N4_WQ) < N4_WK) { src = Wk; dst = g_wkf; off = i; }
    else if ((i -= N4_WK) < N4_WK) { src = Wv; dst = g_wvf; off = i; }
    else if ((i -= N4_WK) < N4_WQ) { src = Wo; dst = g_wof; off = i; }
    else return;
    float4 v = *(const float4*)&src[(size_t)off*4];
    cvt4h_store(v, &dst[(size_t)off*4]);
}

// ---------------- GEMM common (BM128 BN128 BK32, 3-stage, fp16 single) ------
#define GSTR 40
#define G_AF  0
#define G_BF  5120
#define G_STAGE_E 10240   // halves per stage (20480 B)

__device__ __forceinline__ void load_gemm_tile(__half* st,
    const __half* Afg, const __half* Bfg,
    int arow0, int brow0, int kt, int tid)
{
    #pragma unroll
    for (int p = 0; p < 2; p++) {
        int cidx = tid + p*256;
        int row = cidx >> 2, ch = (cidx & 3)*8;
        size_t so = (size_t)(arow0 + row)*HIDD + kt + ch;
        cpa16(&st[G_AF + row*GSTR + ch], Afg + so);
    }
    #pragma unroll
    for (int p = 0; p < 2; p++) {
        int cidx = tid + p*256;
        int row = cidx >> 2, ch = (cidx & 3)*8;
        size_t so = (size_t)(brow0 + row)*HIDD + kt + ch;
        cpa16(&st[G_BF + row*GSTR + ch], Bfg + so);
    }
    cpa_commit();
}

// single-term fp16, accumulator-interleaved
__device__ __forceinline__ void gemm_compute(uint32_t stb,
    float c[4][4][4], int wm, int wn, int gi, int ii)
{
    #pragma unroll
    for (int ks = 0; ks < 2; ks++) {
        uint32_t af[4][4], bf[2][4];
        #pragma unroll
        for (int mi = 0; mi < 4; mi++) {
            int row = wm*64 + mi*16 + ii + (gi & 1)*8;
            int col = ks*16 + (gi >> 1)*8;
            ldsm4(af[mi], stb + (G_AF + row*GSTR + col)*2);
        }
        #pragma unroll
        for (int ng = 0; ng < 2; ng++) {
            int row = wn*32 + ng*16 + ii + (gi >> 1)*8;
            int col = ks*16 + (gi & 1)*8;
            ldsm4(bf[ng], stb + (G_BF + row*GSTR + col)*2);
        }
        #pragma unroll
        for (int mi = 0; mi < 4; mi++)
            #pragma unroll
            for (int ng = 0; ng < 2; ng++) {
                mma16816h(c[mi][2*ng],   af[mi], &bf[ng][0]);
                mma16816h(c[mi][2*ng+1], af[mi], &bf[ng][2]);
            }
    }
}

// ---------------- QKV GEMM ---------------------------------------------------
__global__ __launch_bounds__(256) void qkv_gemm(
    const float* __restrict__ bq, const float* __restrict__ bk, const float* __restrict__ bv)
{
    extern __shared__ __half gsm[];
    const int tid = threadIdx.x, lane = tid & 31, warp = tid >> 5;
    const int wm = warp >> 2, wn = warp & 3;
    const int gi = lane >> 3, ii = lane & 7;
    const int bx = blockIdx.x, by = blockIdx.y;
    const int n0 = bx * 128;
    const uint32_t gb = s2u(gsm);

    const __half* Wf; const float* bias; int noff;
    if (n0 < 1024)      { Wf = g_wqf; bias = bq; noff = 0;    }
    else if (n0 < 1280) { Wf = g_wkf; bias = bk; noff = 1024; }
    else                { Wf = g_wvf; bias = bv; noff = 1280; }

    float c[4][4][4];
    #pragma unroll
    for (int i=0;i<4;i++) for (int j=0;j<4;j++) for (int e=0;e<4;e++) c[i][j][e]=0.f;

    load_gemm_tile(gsm,             g_xf, Wf, by*128, n0 - noff, 0,  tid);
    load_gemm_tile(gsm + G_STAGE_E, g_xf, Wf, by*128, n0 - noff, 32, tid);

    for (int t = 0; t < 32; t++) {
        if (t < 31) cpa_wait1(); else cpa_wait0();
        __syncthreads();
        if (t < 30)
            load_gemm_tile(gsm + ((t+2)%3)*G_STAGE_E, g_xf, Wf,
                           by*128, n0 - noff, (t+2)*32, tid);
        gemm_compute(gb + ((t%3)*G_STAGE_E)*2, c, wm, wn, gi, ii);
    }

    #pragma unroll
    for (int mi = 0; mi < 4; mi++)
        #pragma unroll
        for (int ni = 0; ni < 4; ni++)
            #pragma unroll
            for (int e = 0; e < 4; e++) {
                int m = by*128 + wm*64 + mi*16 + (lane >> 2) + ((e >= 2) ? 8 : 0);
                int n = n0 + wn*32 + ni*8 + 2*(lane & 3) + (e & 1);
                int b_ = m >> 11, s = m & 2047;
                float val = c[mi][ni][e] + bias[n - noff];
                if (n < 1024) {
                    int h = n >> 6, d = n & 63;
                    g_q[(((size_t)b_*NH + h)*SS + s)*HD + d] = val;
                } else if (n < 1280) {
                    int nn = n - 1024; int h = nn >> 6, d = nn & 63;
                    g_k[(((size_t)b_*NKV + h)*SS + s)*HD + d] = val;
                } else {
                    int nn = n - 1280; int h = nn >> 6, d = nn & 63;
                    size_t off = (((size_t)b_*NKV + h)*SS + s)*HD + d;
                    g_vf[off] = __float2half(val);
                }
            }
}

// ---------------- RoPE; q -> single fp16 (scaled), k -> single fp16 ---------
__global__ void rope_all(const float* __restrict__ cos_t,
                         const float* __restrict__ sin_t, int tq, int total)
{
    int idx = blockIdx.x * blockDim.x + threadIdx.x;
    if (idx >= total) return;
    int which = (idx >= tq);
    if (which) idx -= tq;
    int d  = idx & 31;
    int s  = (idx >> 5) & 2047;
    int bh = idx >> 16;
    size_t base = ((size_t)bh*SS + s)*HD;
    const float* src = which ? g_k : g_q;
    __half* dst = which ? g_kf : g_qf;
    float scale = which ? 1.0f : (SCALE_F * LOG2E);
    float x1 = src[base + d], x2 = src[base + d + 32];
    float c1 = cos_t[s*HD + d],      s1 = sin_t[s*HD + d];
    float c2 = cos_t[s*HD + d + 32], s2 = sin_t[s*HD + d + 32];
    dst[base + d]      = __float2half((x1*c1 - x2*s1) * scale);
    dst[base + d + 32] = __float2half((x2*c2 + x1*s2) * scale);
}

// ---------------- flash attention (128 q-rows, 256 thr, 64-key, 3-stage) ----
#define FSTR 72
#define F_ARR (64*FSTR)
#define F_STAGE_E (2*F_ARR)     // Kf, Vf per stage (18432 B)
#define NT (SS/64)

__device__ __forceinline__ void load_kv_tile(__half* st,
    const __half* kfg, const __half* vfg, int t, int tid)
{
    #pragma unroll
    for (int p = 0; p < 2; p++) {
        int cidx = tid + p*256;
        int row = cidx >> 3, ch = (cidx & 7)*8;
        size_t so = ((size_t)t*64 + row)*HD + ch;
        cpa16(&st[        row*FSTR + ch], kfg + so);
        cpa16(&st[F_ARR + row*FSTR + ch], vfg + so);
    }
    cpa_commit();
}

__global__ __launch_bounds__(256) void flash_kernel()
{
    extern __shared__ __half fsm[];

    const int b = blockIdx.z, h = blockIdx.y, qt = blockIdx.x;
    const int tid = threadIdx.x, lane = tid & 31, warp = tid >> 5;
    const int hk = h / GROUPS;
    const int gi = lane >> 3, ii = lane & 7;
    const uint32_t fb = s2u(fsm);

    const __half* qfg = g_qf + (((size_t)b*NH  + h )*SS + qt*128)*HD;
    const __half* kfg = g_kf + (((size_t)b*NKV + hk)*SS)*HD;
    const __half* vfg = g_vf + (((size_t)b*NKV + hk)*SS)*HD;

    // stage Q (128 rows) through stage-0 smem, grab fragments
    {
        #pragma unroll
        for (int p = 0; p < 4; p++) {
            int cidx = tid + p*256;
            int row = cidx >> 3, ch = (cidx & 7)*8;
            size_t so = (size_t)row*HD + ch;
            cpa16(&fsm[row*FSTR + ch], qfg + so);
        }
        cpa_commit();
        cpa_wait0();
        __syncthreads();
    }

    uint32_t qf[4][4];
    #pragma unroll
    for (int kk = 0; kk < 4; kk++) {
        int row = warp*16 + ii + (gi & 1)*8;
        int col = kk*16 + (gi >> 1)*8;
        ldsm4(qf[kk], fb + (row*FSTR + col)*2);
    }
    __syncthreads();   // all frags extracted before stage-0 reuse

    load_kv_tile(fsm,             kfg, vfg, 0, tid);
    load_kv_tile(fsm + F_STAGE_E, kfg, vfg, 1, tid);

    const uint32_t onesb[2] = {0x3C003C00u, 0x3C003C00u};   // fp16 1.0 x4
    float o[8][4];
    #pragma unroll
    for (int i = 0; i < 8; i++) for (int j = 0; j < 4; j++) o[i][j] = 0.f;
    float lacc[4] = {0.f, 0.f, 0.f, 0.f};
    float m0 = -1e30f, m1 = -1e30f;

    for (int t = 0; t < NT; t++) {
        if (t < NT-1) cpa_wait1(); else cpa_wait0();
        __syncthreads();
        if (t < NT-2)
            load_kv_tile(fsm + ((t+2)%3)*F_STAGE_E, kfg, vfg, t+2, tid);

        const uint32_t stb = fb + ((t%3)*F_STAGE_E)*2;

        // S = Q K^T (single fp16)
        float s[8][4];
        #pragma unroll
        for (int i = 0; i < 8; i++) for (int j = 0; j < 4; j++) s[i][j] = 0.f;
        #pragma unroll
        for (int kk = 0; kk < 4; kk++) {
            int col = kk*16 + (gi & 1)*8;
            uint32_t kf[4][4];
            #pragma unroll
            for (int ng = 0; ng < 4; ng++) {
                int row = ng*16 + ii + (gi >> 1)*8;
                ldsm4(kf[ng], stb + (row*FSTR + col)*2);
            }
            #pragma unroll
            for (int ng = 0; ng < 4; ng++) {
                mma16816h(s[2*ng],   qf[kk], &kf[ng][0]);
                mma16816h(s[2*ng+1], qf[kk], &kf[ng][2]);
            }
        }

        // online softmax (exp2 domain)
        float mx0 = -1e30f, mx1 = -1e30f;
        #pragma unroll
        for (int nt = 0; nt < 8; nt++) {
            mx0 = fmaxf(mx0, fmaxf(s[nt][0], s[nt][1]));
            mx1 = fmaxf(mx1, fmaxf(s[nt][2], s[nt][3]));
        }
        mx0 = fmaxf(mx0, __shfl_xor_sync(0xffffffffu, mx0, 1));
        mx0 = fmaxf(mx0, __shfl_xor_sync(0xffffffffu, mx0, 2));
        mx1 = fmaxf(mx1, __shfl_xor_sync(0xffffffffu, mx1, 1));
        mx1 = fmaxf(mx1, __shfl_xor_sync(0xffffffffu, mx1, 2));
        float nm0 = fmaxf(m0, mx0), nm1 = fmaxf(m1, mx1);
        float cr0 = fexp2(m0 - nm0), cr1 = fexp2(m1 - nm1);
        m0 = nm0; m1 = nm1;
        if (__ballot_sync(0xffffffffu, (cr0 < 1.f) | (cr1 < 1.f))) {
            #pragma unroll
            for (int nb = 0; nb < 8; nb++) {
                o[nb][0] *= cr0; o[nb][1] *= cr0;
                o[nb][2] *= cr1; o[nb][3] *= cr1;
            }
            lacc[0] *= cr0; lacc[1] *= cr0;
            lacc[2] *= cr1; lacc[3] *= cr1;
        }

        // P = exp2(s-m) packed fp16; l += P*ones; O += P*V
        #pragma unroll
        for (int ks = 0; ks < 4; ks++) {
            const float* s0 = s[2*ks];
            const float* s1 = s[2*ks+1];
            uint32_t pa[4];
            pa[0] = fexp2h2(s0[0] - m0, s0[1] - m0);
            pa[1] = fexp2h2(s0[2] - m1, s0[3] - m1);
            pa[2] = fexp2h2(s1[0] - m0, s1[1] - m0);
            pa[3] = fexp2h2(s1[2] - m1, s1[3] - m1);

            mma16816h(lacc, pa, onesb);

            int row = ks*16 + ii + (gi & 1)*8;
            uint32_t bv[4][4];
            #pragma unroll
            for (int dg = 0; dg < 4; dg++) {
                int col = dg*16 + (gi >> 1)*8;
                ldsm4t(bv[dg], stb + (F_ARR + row*FSTR + col)*2);
            }
            #pragma unroll
            for (int dg = 0; dg < 4; dg++) {
                mma16816h(o[2*dg],   pa, &bv[dg][0]);
                mma16816h(o[2*dg+1], pa, &bv[dg][2]);
            }
        }
    }

    // finalize (ones-MMA reduced over keys; no shuffles needed)
    float inv0 = 1.f / lacc[0], inv1 = 1.f / lacc[2];

    int r0 = qt*128 + warp*16 + (lane >> 2);
    size_t o0 = ((size_t)b*SS + r0    )*(NH*HD) + h*HD;
    size_t o1 = ((size_t)b*SS + r0 + 8)*(NH*HD) + h*HD;
    #pragma unroll
    for (int nb = 0; nb < 8; nb++) {
        int d = nb*8 + 2*(lane & 3);
        *(__half2*)&g_aof[o0 + d] = __floats2half2_rn(o[nb][0]*inv0, o[nb][1]*inv0);
        *(__half2*)&g_aof[o1 + d] = __floats2half2_rn(o[nb][2]*inv1, o[nb][3]*inv1);
    }
}

// ---------------- O-proj GEMM ----------------------------------------------
__global__ __launch_bounds__(256) void oproj_gemm(
    const float* __restrict__ bo, float* __restrict__ C)
{
    extern __shared__ __half gsm[];
    const int tid = threadIdx.x, lane = tid & 31, warp = tid >> 5;
    const int wm = warp >> 2, wn = warp & 3;
    const int gi = lane >> 3, ii = lane & 7;
    const int bx = blockIdx.x, by = blockIdx.y;
    const int n0 = bx * 128;
    const uint32_t gb = s2u(gsm);

    float c[4][4][4];
    #pragma unroll
    for (int i=0;i<4;i++) for (int j=0;j<4;j++) for (int e=0;e<4;e++) c[i][j][e]=0.f;

    load_gemm_tile(gsm,             g_aof, g_wof, by*128, n0, 0,  tid);
    load_gemm_tile(gsm + G_STAGE_E, g_aof, g_wof, by*128, n0, 32, tid);

    for (int t = 0; t < 32; t++) {
        if (t < 31) cpa_wait1(); else cpa_wait0();
        __syncthreads();
        if (t < 30)
            load_gemm_tile(gsm + ((t+2)%3)*G_STAGE_E, g_aof, g_wof,
                           by*128, n0, (t+2)*32, tid);
        gemm_compute(gb + ((t%3)*G_STAGE_E)*2, c, wm, wn, gi, ii);
    }

    #pragma unroll
    for (int mi = 0; mi < 4; mi++)
        #pragma unroll
        for (int ni = 0; ni < 4; ni++)
            #pragma unroll
            for (int e = 0; e < 4; e++) {
                int m = by*128 + wm*64 + mi*16 + (lane >> 2) + ((e >= 2) ? 8 : 0);
                int n = n0 + wn*32 + ni*8 + 2*(lane & 3) + (e & 1);
                C[(size_t)m*HIDD + n] = c[mi][ni][e] + bo[n];
            }
}

// ---------------------------------------------------------------------------
extern "C" void kernel_launch(void* const* d_in, const int* in_sizes, int n_in,
                              void* d_out, int out_size)
{
    const float* X    = (const float*)d_in[0];
    const float* cosp = (const float*)d_in[1];
    const float* sinp = (const float*)d_in[2];
    const float* Wq   = (const float*)d_in[3];
    const float* bq   = (const float*)d_in[4];
    const float* Wk   = (const float*)d_in[5];
    const float* bk   = (const float*)d_in[6];
    const float* Wv   = (const float*)d_in[7];
    const float* bv   = (const float*)d_in[8];
    const float* Wo   = (const float*)d_in[9];
    const float* bo   = (const float*)d_in[10];
    float* out = (float*)d_out;

    const int gemm_smem  = 3 * G_STAGE_E * (int)sizeof(__half);   // 61440
    const int flash_smem = 3 * F_STAGE_E * (int)sizeof(__half);   // 55296
    cudaFuncSetAttribute(qkv_gemm,    cudaFuncAttributeMaxDynamicSharedMemorySize, gemm_smem);
    cudaFuncSetAttribute(oproj_gemm,  cudaFuncAttributeMaxDynamicSharedMemorySize, gemm_smem);
    cudaFuncSetAttribute(flash_kernel,cudaFuncAttributeMaxDynamicSharedMemorySize, flash_smem);

    int n4_total = N4_X + 2*N4_WQ + 2*N4_WK;
    split_all<<<(n4_total + 255)/256, 256>>>(X, Wq, Wk, Wv, Wo);

    dim3 g1(1536/128, 8192/128);
    qkv_gemm<<<g1, 256, gemm_smem>>>(bq, bk, bv);

    int tq = BB*NH *SS*32;
    int tk = BB*NKV*SS*32;
    rope_all<<<(tq + tk + 255)/256, 256>>>(cosp, sinp, tq, tq + tk);

    dim3 g3(SS/128, NH, BB);
    flash_kernel<<<g3, 256, flash_smem>>>();

    dim3 g4(1024/128, 8192/128);
    oproj_gemm<<<g4, 256, gemm_smem>>>(bo, out);
}